// round 15
// baseline (speedup 1.0000x reference)
#include <cuda_runtime.h>

#define BB 64
#define PP 8732
#define CC 81
#define NPRI (BB*PP)            // 558848
#define TILE 32                 // priors per tile
#define NTHREADS 128            // 4 threads per prior
#define NTILES (NPRI/TILE)      // 17464 exactly
#define K1_GRID 740             // 5 blocks per SM (148 SMs)
#define STG_FLOATS (TILE*CC)    // 2592 per plane
#define STG_WORDS  (2*STG_FLOATS + TILE)
#define STG_BYTES  (STG_WORDS*4)           // 20864
#define SMEM_BYTES (2*STG_WORDS*4)         // 41728 -> 5 blocks/SM

#define K2_THREADS 1024
#define K2_SMEM (32*512*4)      // 64KB warp-private histograms
#define HBASE 0x3F000000u       // 0.5f; lc values live in [~1, ~14] < 128
#define HSHIFT1 17              // L1 bin width 2^17 ulp; 512 bins cover [0.5, 128)

// Scratch (device globals; no allocations allowed)
__device__ float g_lcT[NPRI];
__device__ float g_lcS[NPRI];
__device__ float g_plT[K1_GRID];
__device__ float g_plS[K1_GRID];
__device__ float g_negSum[2*BB];
__device__ float g_posLc[2*BB];
__device__ int   g_numPos[BB];
__device__ unsigned g_done = 0;

// ---- packed f32x2 paired ops (sm_103a has no redux.f32) ----
__device__ __forceinline__ unsigned long long packf2(float a, float b){
    unsigned long long r;
    asm("mov.b64 %0, {%1, %2};" : "=l"(r) : "f"(a), "f"(b));
    return r;
}
__device__ __forceinline__ void unpackf2(unsigned long long v, float& a, float& b){
    asm("mov.b64 {%0, %1}, %2;" : "=f"(a), "=f"(b) : "l"(v));
}
__device__ __forceinline__ unsigned long long addf2(unsigned long long x, unsigned long long y){
    unsigned long long r;
    asm("add.rn.f32x2 %0, %1, %2;" : "=l"(r) : "l"(x), "l"(y));
    return r;
}
__device__ __forceinline__ void warpSum2(float& a, float& b){
    unsigned long long v = packf2(a, b);
#pragma unroll
    for (int o = 16; o; o >>= 1)
        v = addf2(v, __shfl_xor_sync(0xffffffffu, v, o));
    unpackf2(v, a, b);
}
__device__ __forceinline__ float warpSum(float v){
#pragma unroll
    for (int o = 16; o; o >>= 1) v += __shfl_xor_sync(0xffffffffu, v, o);
    return v;
}
__device__ __forceinline__ float sl1(float d){
    d = fabsf(d);
    return d < 1.f ? 0.5f * d * d : d - 0.5f;
}

// ---- mbarrier + 1D bulk-async (UBLKCP) helpers ----
__device__ __forceinline__ void mbar_init(unsigned mb, unsigned cnt){
    asm volatile("mbarrier.init.shared.b64 [%0], %1;" :: "r"(mb), "r"(cnt) : "memory");
}
__device__ __forceinline__ void mbar_expect_tx(unsigned mb, unsigned bytes){
    asm volatile("mbarrier.arrive.expect_tx.shared.b64 _, [%0], %1;" :: "r"(mb), "r"(bytes) : "memory");
}
__device__ __forceinline__ void mbar_wait(unsigned mb, unsigned parity){
    asm volatile(
        "{\n\t.reg .pred P;\n"
        "W_%=:\n\t"
        "mbarrier.try_wait.parity.acquire.cta.shared::cta.b64 P, [%0], %1, 0x989680;\n\t"
        "@P bra D_%=;\n\t"
        "bra W_%=;\n"
        "D_%=:\n\t}"
        :: "r"(mb), "r"(parity) : "memory");
}
__device__ __forceinline__ void bulk_g2s(unsigned sdst, const void* gsrc, unsigned bytes, unsigned mb){
    asm volatile(
        "cp.async.bulk.shared::cluster.global.mbarrier::complete_tx::bytes [%0], [%1], %2, [%3];"
        :: "r"(sdst), "l"(gsrc), "r"(bytes), "r"(mb) : "memory");
}

// ---------------------------------------------------------------------------
// k1 (R10, proven at ~6.24 TB/s effective ceiling). UNCHANGED.
// ---------------------------------------------------------------------------
__global__ __launch_bounds__(NTHREADS, 5) void k1(
    const float* __restrict__ locT, const float* __restrict__ confT,
    const float* __restrict__ locS, const float* __restrict__ confS,
    const float* __restrict__ loct, const int*   __restrict__ conft)
{
    extern __shared__ float smf[];
    __shared__ unsigned long long mbar[2];
    const int tid = threadIdx.x;
    const unsigned sbase = (unsigned)__cvta_generic_to_shared(smf);
    const unsigned mb0 = (unsigned)__cvta_generic_to_shared(&mbar[0]);

    if (tid == 0) { mbar_init(mb0, 1); mbar_init(mb0 + 8, 1); }
    __syncthreads();

    auto issue = [&](int t, int stg) {
        if (tid == 0) {
            const unsigned mb = mb0 + (unsigned)stg * 8;
            mbar_expect_tx(mb, STG_BYTES);
            const unsigned sb = sbase + (unsigned)stg * STG_BYTES;
            const char* gT = (const char*)confT + (size_t)t * (TILE * CC * 4);
            const char* gS = (const char*)confS + (size_t)t * (TILE * CC * 4);
            bulk_g2s(sb,                      gT, STG_FLOATS * 4, mb);
            bulk_g2s(sb + STG_FLOATS * 4,     gS, STG_FLOATS * 4, mb);
            bulk_g2s(sb + 2 * STG_FLOATS * 4, conft + (size_t)t * TILE, TILE * 4, mb);
        }
    };

    float accT = 0.f, accS = 0.f;

    int t = blockIdx.x;
    if (t < NTILES) issue(t, 0);
    int stage = 0;
    int ph0 = 0, ph1 = 0;

    const int p = tid >> 2;
    const int q = tid & 3;

    for (; t < NTILES; t += K1_GRID) {
        const int nxt = t + K1_GRID;
        if (nxt < NTILES) issue(nxt, stage ^ 1);

        if (stage == 0) { mbar_wait(mb0, ph0);     ph0 ^= 1; }
        else            { mbar_wait(mb0 + 8, ph1); ph1 ^= 1; }

        const float* rowT = smf + stage * STG_WORDS + p * CC;
        const float* rowS = rowT + STG_FLOATS;

        float eT0 = 0.f, eT1 = 0.f, eS0 = 0.f, eS1 = 0.f;
        #pragma unroll
        for (int i = 0; i < 20; i += 2) {
            const int c = q + 4 * i;
            eT0 += __expf(rowT[c]);     eS0 += __expf(rowS[c]);
            eT1 += __expf(rowT[c + 4]); eS1 += __expf(rowS[c + 4]);
        }
        float eT = eT0 + eT1, eS = eS0 + eS1;
        if (q == 0) { eT += __expf(rowT[80]); eS += __expf(rowS[80]); }

        unsigned long long v = packf2(eT, eS);
        v = addf2(v, __shfl_xor_sync(0xffffffffu, v, 1));
        v = addf2(v, __shfl_xor_sync(0xffffffffu, v, 2));
        unpackf2(v, eT, eS);

        if (q == 0) {
            const int gt = ((const int*)(smf + stage * STG_WORDS + 2 * STG_FLOATS))[p];
            const int gp = t * TILE + p;
            g_lcT[gp] = __logf(eT) - rowT[gt];
            g_lcS[gp] = __logf(eS) - rowS[gt];

            if (gt > 0) {
                const float4 vt = __ldg((const float4*)loct + gp);
                const float4 aT = __ldg((const float4*)locT + gp);
                const float4 aS = __ldg((const float4*)locS + gp);
                accT += sl1(aT.x - vt.x) + sl1(aT.y - vt.y) + sl1(aT.z - vt.z) + sl1(aT.w - vt.w);
                accS += sl1(aS.x - vt.x) + sl1(aS.y - vt.y) + sl1(aS.z - vt.z) + sl1(aS.w - vt.w);
            }
        }
        __syncthreads();
        stage ^= 1;
    }

    warpSum2(accT, accS);
    __shared__ float rT[4], rS[4];
    const int wid = tid >> 5, lane = tid & 31;
    if (lane == 0) { rT[wid] = accT; rS[wid] = accS; }
    __syncthreads();
    if (tid == 0) {
        g_plT[blockIdx.x] = rT[0] + rT[1] + rT[2] + rT[3];
        g_plS[blockIdx.x] = rS[0] + rS[1] + rS[2] + rS[3];
    }
}

// ---------------------------------------------------------------------------
// k2: hard-negative mining per (row, branch) — R13 structure (proven exact:
// two-level histogram select + tie-correction) with two changes:
//  (a) 1024 threads (9 keys/thread: [8*tid,8*tid+8) + guarded 8192+tid tail;
//      full 8732-key coverage) -> 2x load MLP, half the per-thread passes.
//  (b) L1 histogram is WARP-PRIVATE and NON-ATOMIC: 32 warps x 512 bins in
//      64KB smem; __match_any_sync dedupes equal bins within the warp and
//      the leader does LDS+add+STS (replaces 18 ATOMS/thread -> no atomic
//      serialization, no RMW race). Merge = 512 threads sum 32 copies.
//  L2: 512 bins of width 2^8 inside the exact bin (atomics, few keys).
//  Sum of top-k = sum(x > v) + (k - cgt)*v  (exact tie/window correction).
//  lc >= 0 so uint order == float order. Fused last-block output reduction.
// ---------------------------------------------------------------------------
__global__ __launch_bounds__(K2_THREADS) void k2(const int* __restrict__ conft,
                                                 float* __restrict__ out)
{
    extern __shared__ unsigned whist[];            // [32][512] warp-private
    __shared__ unsigned hist2[512];
    __shared__ unsigned wtot[16];
    __shared__ float fred[32];
    __shared__ int   ired[32];
    __shared__ int   s_npos;
    __shared__ float s_plc;
    __shared__ int   s_selBin, s_kp, s_selBin2;
    __shared__ unsigned s_isLast;

    const int row   = blockIdx.x;
    const int which = blockIdx.y;                 // 0 = teacher, 1 = student
    const float* lc = which ? g_lcS : g_lcT;
    const size_t base = (size_t)row * PP;
    const int tid  = threadIdx.x;
    const int wid  = tid >> 5, lane = tid & 31;

    // zero warp-private histograms (16 words per thread) + hist2
    #pragma unroll
    for (int j = 0; j < 16; ++j) whist[tid + 1024 * j] = 0u;
    if (tid < 512) hist2[tid] = 0u;
    if (tid == 0) s_selBin2 = 0;

    // ---- load all 8732 keys: [8*tid, 8*tid+8) vectorized + guarded tail
    unsigned key[9];
    int npos = 0; float plc = 0.f;
    {
        const float4* lc4 = (const float4*)(lc + base);
        const int4*   ct4 = (const int4*)(conft + base);
        #pragma unroll
        for (int j = 0; j < 2; ++j) {
            const float4 a = lc4[2 * tid + j];
            const int4   c = ct4[2 * tid + j];
            const float va[4] = {a.x, a.y, a.z, a.w};
            const int   ca[4] = {c.x, c.y, c.z, c.w};
            #pragma unroll
            for (int e = 0; e < 4; ++e) {
                float v = va[e];
                if (ca[e] > 0) { npos++; plc += v; v = 0.f; }
                key[4 * j + e] = __float_as_uint(v);
            }
        }
        unsigned x8 = 0u;
        if (tid < PP - 8192) {               // tail 8192..8731, full coverage
            const int idx = 8192 + tid;
            float v = lc[base + idx];
            if (conft[base + idx] > 0) { npos++; plc += v; v = 0.f; }
            x8 = __float_as_uint(v);
        }
        key[8] = x8;
    }

    npos = __reduce_add_sync(0xffffffffu, npos);
    plc  = warpSum(plc);
    if (lane == 0) { ired[wid] = npos; fred[wid] = plc; }
    __syncthreads();                        // hist zero + ired/fred visible

    // ---- L1 histogram: warp-private, match_any dedup, no atomics
    {
        unsigned* myh = whist + (unsigned)wid * 512u;
        #pragma unroll
        for (int t = 0; t < 9; ++t) {
            const int d0 = (int)key[t] - (int)HBASE;
            const unsigned bin = (unsigned)(d0 < 0 ? 0 : min(d0 >> HSHIFT1, 511));
            const unsigned mask = __match_any_sync(0xffffffffu, bin);
            const int leader = __ffs(mask) - 1;
            const unsigned cnt = (unsigned)__popc(mask);
            if (lane == leader) myh[bin] += cnt;
        }
    }
    if (tid < 32) {
        int c   = __reduce_add_sync(0xffffffffu, ired[tid]);
        float f = warpSum(fred[tid]);
        if (tid == 0) { s_npos = c; s_plc = f; }
    }
    __syncthreads();                        // histograms + s_npos complete
    const int   nposT = s_npos;
    const float plcT  = s_plc;
    const int   k     = min(3 * nposT, PP - 1);

    // ---- merge 32 warp-histograms + L1 suffix scan -> exact bin + rank kp
    {
        unsigned mval = 0u;
        if (tid < 512) {
            #pragma unroll
            for (int w = 0; w < 32; ++w) mval += whist[w * 512 + tid];
        }
        unsigned val = mval;
        #pragma unroll
        for (int o = 1; o < 32; o <<= 1) {
            const unsigned tv = __shfl_down_sync(0xffffffffu, val, o);
            if (lane < 32 - o) val += tv;
        }
        if (lane == 0 && wid < 16) wtot[wid] = val;
        __syncthreads();
        if (tid < 512) {
            unsigned above = 0u;
            #pragma unroll
            for (int w = 0; w < 16; ++w) if (w > wid) above += wtot[w];
            const unsigned sfx = val + above;      // count(bin >= tid)
            if (k > 0 && (int)sfx >= k && (int)(sfx - mval) < k) {
                s_selBin = tid;
                s_kp     = k - (int)(sfx - mval);  // rank within the bin
            }
        }
    }
    __syncthreads();
    const int      selBin = s_selBin;
    const unsigned binLo  = HBASE + ((unsigned)selBin << HSHIFT1);
    const int      kp     = s_kp;

    // ---- L2 histogram: keys whose L1 bin == selBin (few block-wide; atomics)
    if (k > 0) {
        #pragma unroll
        for (int t = 0; t < 9; ++t) {
            const unsigned x = key[t];
            const int d0 = (int)x - (int)HBASE;
            const int i1 = d0 < 0 ? 0 : min(d0 >> HSHIFT1, 511);
            if (i1 == selBin) {
                int d = (int)(x - binLo);
                d = d < 0 ? 0 : d;
                atomicAdd(&hist2[min(d >> 8, 511)], 1u);
            }
        }
    }
    __syncthreads();

    // ---- L2 suffix scan with rank kp -> v
    {
        unsigned h2 = (tid < 512) ? hist2[tid] : 0u;
        unsigned val = h2;
        #pragma unroll
        for (int o = 1; o < 32; o <<= 1) {
            const unsigned tv = __shfl_down_sync(0xffffffffu, val, o);
            if (lane < 32 - o) val += tv;
        }
        if (lane == 0 && wid < 16) wtot[wid] = val;
        __syncthreads();
        if (tid < 512) {
            unsigned above = 0u;
            #pragma unroll
            for (int w = 0; w < 16; ++w) if (w > wid) above += wtot[w];
            const unsigned sfx = val + above;
            if (k > 0 && (int)sfx >= kp && (int)(sfx - h2) < kp) s_selBin2 = tid;
        }
    }
    __syncthreads();
    const unsigned v = binLo + ((unsigned)s_selBin2 << 8);

    // ---- selection sum: strictly-greater + correction
    float sgt = 0.f; int cgt = 0;
    #pragma unroll
    for (int t = 0; t < 9; ++t) {
        const unsigned x = key[t];
        if (x > v) { sgt += __uint_as_float(x); cgt++; }
    }
    sgt = warpSum(sgt);
    cgt = __reduce_add_sync(0xffffffffu, cgt);
    if (lane == 0) { fred[wid] = sgt; ired[wid] = cgt; }
    __syncthreads();
    if (tid == 0) {
        float S = 0.f; int Cg = 0;
        for (int w = 0; w < 32; ++w) { S += fred[w]; Cg += ired[w]; }
        const float res = (k > 0) ? (S + (float)(k - Cg) * __uint_as_float(v)) : 0.f;
        g_negSum[which * BB + row] = res;
        g_posLc [which * BB + row] = plcT;
        if (which == 0) g_numPos[row] = nposT;
        __threadfence();
        s_isLast = (atomicAdd(&g_done, 1u) == 2u * BB - 1u);
    }
    __syncthreads();

    // -------- fused final reduction, done by the last block --------
    if (s_isLast) {
        __threadfence();
        float slT = 0.f, slS = 0.f;
        for (int i = tid; i < K1_GRID; i += K2_THREADS) { slT += g_plT[i]; slS += g_plS[i]; }
        float scT = 0.f, scS = 0.f; int n = 0;
        for (int i = tid; i < BB; i += K2_THREADS) {
            scT += g_posLc[i]      + g_negSum[i];
            scS += g_posLc[BB + i] + g_negSum[BB + i];
            n   += g_numPos[i];
        }
        warpSum2(slT, slS);
        warpSum2(scT, scS);
        n = __reduce_add_sync(0xffffffffu, n);

        __shared__ float r0[32], r1[32], r2[32], r3[32];
        __shared__ int   r4[32];
        if (lane == 0) { r0[wid] = slT; r1[wid] = slS; r2[wid] = scT; r3[wid] = scS; r4[wid] = n; }
        __syncthreads();
        if (tid == 0) {
            float a = 0, b = 0, c = 0, d = 0; int N = 0;
            for (int w = 0; w < 32; ++w) { a += r0[w]; b += r1[w]; c += r2[w]; d += r3[w]; N += r4[w]; }
            const float fN = (float)N;
            out[0] = a / fN;   // loss_lT / N
            out[1] = c / fN;   // loss_cT / N
            out[2] = b / fN;   // loss_lS / N
            out[3] = d / fN;   // loss_cS / N
            g_done = 0;        // reset for next graph replay
        }
    }
}

extern "C" void kernel_launch(void* const* d_in, const int* in_sizes, int n_in,
                              void* d_out, int out_size)
{
    const float* locT  = (const float*)d_in[0];
    const float* confT = (const float*)d_in[1];
    const float* locS  = (const float*)d_in[2];
    const float* confS = (const float*)d_in[3];
    const float* loct  = (const float*)d_in[4];
    const int*   conft = (const int*)  d_in[5];

    // Opt-in to >48KB dynamic smem (idempotent; not a stream op).
    cudaFuncSetAttribute(k1, cudaFuncAttributeMaxDynamicSharedMemorySize, SMEM_BYTES);
    cudaFuncSetAttribute(k2, cudaFuncAttributeMaxDynamicSharedMemorySize, K2_SMEM);

    k1<<<K1_GRID, NTHREADS, SMEM_BYTES>>>(locT, confT, locS, confS, loct, conft);
    dim3 g2(BB, 2);
    k2<<<g2, K2_THREADS, K2_SMEM>>>(conft, (float*)d_out);
}

// round 16
// speedup vs baseline: 1.0837x; 1.0837x over previous
#include <cuda_runtime.h>

#define BB 64
#define PP 8732
#define CC 81
#define NPRI (BB*PP)            // 558848
#define TILE 32                 // priors per tile
#define NTHREADS 128            // 4 threads per prior
#define NTILES (NPRI/TILE)      // 17464 exactly
#define K1_GRID 740             // 5 blocks per SM (148 SMs)
#define STG_FLOATS (TILE*CC)    // 2592 per plane
#define STG_WORDS  (2*STG_FLOATS + TILE)
#define STG_BYTES  (STG_WORDS*4)           // 20864
#define SMEM_BYTES (2*STG_WORDS*4)         // 41728 -> 5 blocks/SM

#define K2_THREADS 512
#define HBASE 0x3F000000u       // 0.5f; lc values live in [~1, ~14] < 128
#define HSHIFT1 17              // L1 bin width 2^17 ulp; 512 bins cover [0.5, 128)

// Scratch (device globals; no allocations allowed)
__device__ float g_lcT[NPRI];
__device__ float g_lcS[NPRI];
__device__ float g_plT[K1_GRID];
__device__ float g_plS[K1_GRID];
__device__ float g_negSum[2*BB];
__device__ float g_posLc[2*BB];
__device__ int   g_numPos[BB];
__device__ unsigned g_done = 0;

// ---- packed f32x2 paired ops (sm_103a has no redux.f32) ----
__device__ __forceinline__ unsigned long long packf2(float a, float b){
    unsigned long long r;
    asm("mov.b64 %0, {%1, %2};" : "=l"(r) : "f"(a), "f"(b));
    return r;
}
__device__ __forceinline__ void unpackf2(unsigned long long v, float& a, float& b){
    asm("mov.b64 {%0, %1}, %2;" : "=f"(a), "=f"(b) : "l"(v));
}
__device__ __forceinline__ unsigned long long addf2(unsigned long long x, unsigned long long y){
    unsigned long long r;
    asm("add.rn.f32x2 %0, %1, %2;" : "=l"(r) : "l"(x), "l"(y));
    return r;
}
__device__ __forceinline__ void warpSum2(float& a, float& b){
    unsigned long long v = packf2(a, b);
#pragma unroll
    for (int o = 16; o; o >>= 1)
        v = addf2(v, __shfl_xor_sync(0xffffffffu, v, o));
    unpackf2(v, a, b);
}
__device__ __forceinline__ float warpSum(float v){
#pragma unroll
    for (int o = 16; o; o >>= 1) v += __shfl_xor_sync(0xffffffffu, v, o);
    return v;
}
__device__ __forceinline__ float sl1(float d){
    d = fabsf(d);
    return d < 1.f ? 0.5f * d * d : d - 0.5f;
}

// ---- mbarrier + 1D bulk-async (UBLKCP) helpers ----
__device__ __forceinline__ void mbar_init(unsigned mb, unsigned cnt){
    asm volatile("mbarrier.init.shared.b64 [%0], %1;" :: "r"(mb), "r"(cnt) : "memory");
}
__device__ __forceinline__ void mbar_expect_tx(unsigned mb, unsigned bytes){
    asm volatile("mbarrier.arrive.expect_tx.shared.b64 _, [%0], %1;" :: "r"(mb), "r"(bytes) : "memory");
}
__device__ __forceinline__ void mbar_wait(unsigned mb, unsigned parity){
    asm volatile(
        "{\n\t.reg .pred P;\n"
        "W_%=:\n\t"
        "mbarrier.try_wait.parity.acquire.cta.shared::cta.b64 P, [%0], %1, 0x989680;\n\t"
        "@P bra D_%=;\n\t"
        "bra W_%=;\n"
        "D_%=:\n\t}"
        :: "r"(mb), "r"(parity) : "memory");
}
__device__ __forceinline__ void bulk_g2s(unsigned sdst, const void* gsrc, unsigned bytes, unsigned mb){
    asm volatile(
        "cp.async.bulk.shared::cluster.global.mbarrier::complete_tx::bytes [%0], [%1], %2, [%3];"
        :: "r"(sdst), "l"(gsrc), "r"(bytes), "r"(mb) : "memory");
}

// ---------------------------------------------------------------------------
// k1 (R10, proven at ~6.24 TB/s effective ceiling). UNCHANGED.
// ---------------------------------------------------------------------------
__global__ __launch_bounds__(NTHREADS, 5) void k1(
    const float* __restrict__ locT, const float* __restrict__ confT,
    const float* __restrict__ locS, const float* __restrict__ confS,
    const float* __restrict__ loct, const int*   __restrict__ conft)
{
    extern __shared__ float smf[];
    __shared__ unsigned long long mbar[2];
    const int tid = threadIdx.x;
    const unsigned sbase = (unsigned)__cvta_generic_to_shared(smf);
    const unsigned mb0 = (unsigned)__cvta_generic_to_shared(&mbar[0]);

    if (tid == 0) { mbar_init(mb0, 1); mbar_init(mb0 + 8, 1); }
    __syncthreads();

    auto issue = [&](int t, int stg) {
        if (tid == 0) {
            const unsigned mb = mb0 + (unsigned)stg * 8;
            mbar_expect_tx(mb, STG_BYTES);
            const unsigned sb = sbase + (unsigned)stg * STG_BYTES;
            const char* gT = (const char*)confT + (size_t)t * (TILE * CC * 4);
            const char* gS = (const char*)confS + (size_t)t * (TILE * CC * 4);
            bulk_g2s(sb,                      gT, STG_FLOATS * 4, mb);
            bulk_g2s(sb + STG_FLOATS * 4,     gS, STG_FLOATS * 4, mb);
            bulk_g2s(sb + 2 * STG_FLOATS * 4, conft + (size_t)t * TILE, TILE * 4, mb);
        }
    };

    float accT = 0.f, accS = 0.f;

    int t = blockIdx.x;
    if (t < NTILES) issue(t, 0);
    int stage = 0;
    int ph0 = 0, ph1 = 0;

    const int p = tid >> 2;
    const int q = tid & 3;

    for (; t < NTILES; t += K1_GRID) {
        const int nxt = t + K1_GRID;
        if (nxt < NTILES) issue(nxt, stage ^ 1);

        if (stage == 0) { mbar_wait(mb0, ph0);     ph0 ^= 1; }
        else            { mbar_wait(mb0 + 8, ph1); ph1 ^= 1; }

        const float* rowT = smf + stage * STG_WORDS + p * CC;
        const float* rowS = rowT + STG_FLOATS;

        float eT0 = 0.f, eT1 = 0.f, eS0 = 0.f, eS1 = 0.f;
        #pragma unroll
        for (int i = 0; i < 20; i += 2) {
            const int c = q + 4 * i;
            eT0 += __expf(rowT[c]);     eS0 += __expf(rowS[c]);
            eT1 += __expf(rowT[c + 4]); eS1 += __expf(rowS[c + 4]);
        }
        float eT = eT0 + eT1, eS = eS0 + eS1;
        if (q == 0) { eT += __expf(rowT[80]); eS += __expf(rowS[80]); }

        unsigned long long v = packf2(eT, eS);
        v = addf2(v, __shfl_xor_sync(0xffffffffu, v, 1));
        v = addf2(v, __shfl_xor_sync(0xffffffffu, v, 2));
        unpackf2(v, eT, eS);

        if (q == 0) {
            const int gt = ((const int*)(smf + stage * STG_WORDS + 2 * STG_FLOATS))[p];
            const int gp = t * TILE + p;
            g_lcT[gp] = __logf(eT) - rowT[gt];
            g_lcS[gp] = __logf(eS) - rowS[gt];

            if (gt > 0) {
                const float4 vt = __ldg((const float4*)loct + gp);
                const float4 aT = __ldg((const float4*)locT + gp);
                const float4 aS = __ldg((const float4*)locS + gp);
                accT += sl1(aT.x - vt.x) + sl1(aT.y - vt.y) + sl1(aT.z - vt.z) + sl1(aT.w - vt.w);
                accS += sl1(aS.x - vt.x) + sl1(aS.y - vt.y) + sl1(aS.z - vt.z) + sl1(aS.w - vt.w);
            }
        }
        __syncthreads();
        stage ^= 1;
    }

    warpSum2(accT, accS);
    __shared__ float rT[4], rS[4];
    const int wid = tid >> 5, lane = tid & 31;
    if (lane == 0) { rT[wid] = accT; rS[wid] = accS; }
    __syncthreads();
    if (tid == 0) {
        g_plT[blockIdx.x] = rT[0] + rT[1] + rT[2] + rT[3];
        g_plS[blockIdx.x] = rS[0] + rS[1] + rS[2] + rS[3];
    }
}

// ---------------------------------------------------------------------------
// k2: R13 structure verbatim (proven 10.8us, exact: two-level histogram
// select + tie-correction) with ONE change: the L1 histogram is 4-WAY
// REPLICATED (hist1[4][512], warp w -> copy w&3). lc values concentrate in
// ~80 hot bins (~115 hits each), so R13's cost was atomic CONTENTION;
// replication divides it by 4. Merge is folded into the suffix-scan read
// (4-term sum). R15's warp-private/match_any variant regressed (64KB zeroing
// + 32-LDS merge); this keeps R13's cheap structure.
//  L2: 512 bins of width 2^8 inside the exact bin; v within 2^8 ulp;
//  sum of top-k = sum(x > v) + (k - cgt)*v (exact tie/window correction).
//  lc >= 0 so uint order == float order. All 8732 keys loaded.
//  Final 4-scalar reduction fused via last-block-done (no k3 launch).
// ---------------------------------------------------------------------------
__global__ __launch_bounds__(K2_THREADS) void k2(const int* __restrict__ conft,
                                                 float* __restrict__ out)
{
    __shared__ unsigned hist1[4][512];             // 4-way replicated L1
    __shared__ unsigned hist2[512];
    __shared__ unsigned wtot[16];
    __shared__ float fred[16];
    __shared__ int   ired[16];
    __shared__ int   s_npos;
    __shared__ float s_plc;
    __shared__ int   s_selBin, s_kp, s_selBin2;
    __shared__ unsigned s_isLast;

    const int row   = blockIdx.x;
    const int which = blockIdx.y;                 // 0 = teacher, 1 = student
    const float* lc = which ? g_lcS : g_lcT;
    const size_t base = (size_t)row * PP;
    const int tid  = threadIdx.x;
    const int wid  = tid >> 5, lane = tid & 31;
    const int hcp  = wid & 3;                     // this warp's histogram copy

    hist1[0][tid] = 0u;
    hist1[1][tid] = 0u;
    hist1[2][tid] = 0u;
    hist1[3][tid] = 0u;
    hist2[tid] = 0u;
    if (tid == 0) s_selBin2 = 0;

    // ---- load all 8732 keys: key[4j+e] = idx 16*tid+(4j+e), + 2 guarded tails
    unsigned key[18];
    int npos = 0; float plc = 0.f;
    {
        const float4* lc4 = (const float4*)(lc + base);
        const int4*   ct4 = (const int4*)(conft + base);
        #pragma unroll
        for (int j = 0; j < 4; ++j) {
            const float4 a = lc4[4 * tid + j];
            const int4   c = ct4[4 * tid + j];
            const float va[4] = {a.x, a.y, a.z, a.w};
            const int   ca[4] = {c.x, c.y, c.z, c.w};
            #pragma unroll
            for (int e = 0; e < 4; ++e) {
                float v = va[e];
                if (ca[e] > 0) { npos++; plc += v; v = 0.f; }
                key[4 * j + e] = __float_as_uint(v);
            }
        }
        #pragma unroll
        for (int jj = 0; jj < 2; ++jj) {
            const int idx = 8192 + tid + 512 * jj;
            unsigned x = 0u;
            if (idx < PP) {
                float v = lc[base + idx];
                if (conft[base + idx] > 0) { npos++; plc += v; v = 0.f; }
                x = __float_as_uint(v);
            }
            key[16 + jj] = x;
        }
    }

    npos = __reduce_add_sync(0xffffffffu, npos);
    plc  = warpSum(plc);
    if (lane == 0) { ired[wid] = npos; fred[wid] = plc; }
    __syncthreads();                           // hist zero + ired/fred visible

    // ---- L1 histogram into this warp's replica (contention / 4)
    #pragma unroll
    for (int t = 0; t < 18; ++t) {
        const int d0 = (int)key[t] - (int)HBASE;
        const int idx = d0 < 0 ? 0 : min(d0 >> HSHIFT1, 511);
        atomicAdd(&hist1[hcp][idx], 1u);
    }
    if (tid < 16) {
        int c   = __reduce_add_sync(0xffffu, ired[tid]);
        float f = fred[tid];
        #pragma unroll
        for (int o = 8; o; o >>= 1) f += __shfl_xor_sync(0xffffu, f, o);
        if (tid == 0) { s_npos = c; s_plc = f; }
    }
    __syncthreads();                           // hist1 atomics + s_npos done
    const int   nposT = s_npos;
    const float plcT  = s_plc;
    const int   k     = min(3 * nposT, PP - 1);

    // ---- L1 merge (4-term) + suffix scan -> crossing bin + in-bin rank
    {
        const unsigned mval = hist1[0][tid] + hist1[1][tid]
                            + hist1[2][tid] + hist1[3][tid];
        unsigned val = mval;
        #pragma unroll
        for (int o = 1; o < 32; o <<= 1) {
            const unsigned tv = __shfl_down_sync(0xffffffffu, val, o);
            if (lane < 32 - o) val += tv;
        }
        if (lane == 0) wtot[wid] = val;        // warp-total (suffix at lane 0)
        __syncthreads();
        unsigned above = 0u;
        #pragma unroll
        for (int w = 0; w < 16; ++w) if (w > wid) above += wtot[w];
        const unsigned sfx = val + above;      // count(bin >= tid)
        if (k > 0 && (int)sfx >= k && (int)(sfx - mval) < k) {
            s_selBin = tid;
            s_kp     = k - (int)(sfx - mval);  // rank within the bin
        }
    }
    __syncthreads();
    const int      selBin = s_selBin;
    const unsigned binLo  = HBASE + ((unsigned)selBin << HSHIFT1);
    const int      kp     = s_kp;

    // ---- L2 histogram: keys whose L1 bin == selBin, 512 bins of width 2^8
    #pragma unroll
    for (int t = 0; t < 18; ++t) {
        const unsigned x = key[t];
        const int d0 = (int)x - (int)HBASE;
        const int i1 = d0 < 0 ? 0 : min(d0 >> HSHIFT1, 511);
        if (i1 == selBin) {
            int d = (int)(x - binLo);
            d = d < 0 ? 0 : d;
            atomicAdd(&hist2[min(d >> 8, 511)], 1u);
        }
    }
    __syncthreads();

    // ---- L2 suffix scan + crossing -> v
    {
        unsigned val = hist2[tid];
        #pragma unroll
        for (int o = 1; o < 32; o <<= 1) {
            const unsigned tv = __shfl_down_sync(0xffffffffu, val, o);
            if (lane < 32 - o) val += tv;
        }
        if (lane == 0) wtot[wid] = val;
        __syncthreads();
        unsigned above = 0u;
        #pragma unroll
        for (int w = 0; w < 16; ++w) if (w > wid) above += wtot[w];
        const unsigned sfx = val + above;
        if (k > 0 && (int)sfx >= kp && (int)(sfx - hist2[tid]) < kp)
            s_selBin2 = tid;
    }
    __syncthreads();
    const unsigned v = binLo + ((unsigned)s_selBin2 << 8);

    // ---- selection sum: strictly-greater + correction
    float sgt = 0.f; int cgt = 0;
    #pragma unroll
    for (int t = 0; t < 18; ++t) {
        const unsigned x = key[t];
        if (x > v) { sgt += __uint_as_float(x); cgt++; }
    }
    sgt = warpSum(sgt);
    cgt = __reduce_add_sync(0xffffffffu, cgt);
    if (lane == 0) { fred[wid] = sgt; ired[wid] = cgt; }
    __syncthreads();
    if (tid == 0) {
        float S = 0.f; int Cg = 0;
        for (int w = 0; w < 16; ++w) { S += fred[w]; Cg += ired[w]; }
        const float res = (k > 0) ? (S + (float)(k - Cg) * __uint_as_float(v)) : 0.f;
        g_negSum[which * BB + row] = res;
        g_posLc [which * BB + row] = plcT;
        if (which == 0) g_numPos[row] = nposT;
        __threadfence();
        s_isLast = (atomicAdd(&g_done, 1u) == 2u * BB - 1u);
    }
    __syncthreads();

    // -------- fused final reduction, done by the last block --------
    if (s_isLast) {
        __threadfence();
        float slT = 0.f, slS = 0.f;
        for (int i = tid; i < K1_GRID; i += K2_THREADS) { slT += g_plT[i]; slS += g_plS[i]; }
        float scT = 0.f, scS = 0.f; int n = 0;
        for (int i = tid; i < BB; i += K2_THREADS) {
            scT += g_posLc[i]      + g_negSum[i];
            scS += g_posLc[BB + i] + g_negSum[BB + i];
            n   += g_numPos[i];
        }
        warpSum2(slT, slS);
        warpSum2(scT, scS);
        n = __reduce_add_sync(0xffffffffu, n);

        __shared__ float r0[16], r1[16], r2[16], r3[16];
        __shared__ int   r4[16];
        if (lane == 0) { r0[wid] = slT; r1[wid] = slS; r2[wid] = scT; r3[wid] = scS; r4[wid] = n; }
        __syncthreads();
        if (tid == 0) {
            float a = 0, b = 0, c = 0, d = 0; int N = 0;
            for (int w = 0; w < 16; ++w) { a += r0[w]; b += r1[w]; c += r2[w]; d += r3[w]; N += r4[w]; }
            const float fN = (float)N;
            out[0] = a / fN;   // loss_lT / N
            out[1] = c / fN;   // loss_cT / N
            out[2] = b / fN;   // loss_lS / N
            out[3] = d / fN;   // loss_cS / N
            g_done = 0;        // reset for next graph replay
        }
    }
}

extern "C" void kernel_launch(void* const* d_in, const int* in_sizes, int n_in,
                              void* d_out, int out_size)
{
    const float* locT  = (const float*)d_in[0];
    const float* confT = (const float*)d_in[1];
    const float* locS  = (const float*)d_in[2];
    const float* confS = (const float*)d_in[3];
    const float* loct  = (const float*)d_in[4];
    const int*   conft = (const int*)  d_in[5];

    // Opt-in to >48KB dynamic smem (idempotent; not a stream op).
    cudaFuncSetAttribute(k1, cudaFuncAttributeMaxDynamicSharedMemorySize, SMEM_BYTES);

    k1<<<K1_GRID, NTHREADS, SMEM_BYTES>>>(locT, confT, locS, confS, loct, conft);
    dim3 g2(BB, 2);
    k2<<<g2, K2_THREADS>>>(conft, (float*)d_out);
}